// round 10
// baseline (speedup 1.0000x reference)
#include <cuda_runtime.h>

#define cB 2
#define cN 2048
#define cDIM 1024
#define cH 16
#define cD 64
#define cE 3072      // 3*DIM
#define cM 4096      // B*N
#define cK 1024

// Scratch: q,k,v in [B,H,N,D] layout (16 MB each)
__device__ float g_q[cB * cH * cN * cD];
__device__ float g_k[cB * cH * cN * cD];
__device__ float g_v[cB * cH * cN * cD];

// ---- tf32 helpers ----------------------------------------------------------
__device__ __forceinline__ unsigned f2tf32(float x) {
    unsigned r;
    asm("cvt.rna.tf32.f32 %0, %1;" : "=r"(r) : "f"(x));
    return r;
}
// D += A * B  (m16n8k8 tf32)
__device__ __forceinline__ void mma_tf32(float* cc, const unsigned* a,
                                         unsigned b0, unsigned b1) {
    asm volatile(
        "mma.sync.aligned.m16n8k8.row.col.f32.tf32.tf32.f32 "
        "{%0,%1,%2,%3}, {%4,%5,%6,%7}, {%8,%9}, {%0,%1,%2,%3};"
        : "+f"(cc[0]), "+f"(cc[1]), "+f"(cc[2]), "+f"(cc[3])
        : "r"(a[0]), "r"(a[1]), "r"(a[2]), "r"(a[3]), "r"(b0), "r"(b1));
}

// ---------------------------------------------------------------------------
// Kernel 1: qkv = x @ W^T + b via split-tf32 tensor-core mma.
// CTA tile 128m x 64e, BK=16, 256 threads = 8 warps, each warp 16x64
// (1 m-tile x 8 n-tiles of m16n8k8). acc = 32 regs/thread -> <=128 regs
// -> 2 CTAs/SM (16 warps) for latency hiding. Smem 25.6KB static.
// Split precision: v = hi + lo (both tf32); D += Ahi*Bhi + Ahi*Blo + Alo*Bhi
// -> ~2^-22 relative error.
// ---------------------------------------------------------------------------
#define GPA 132   // A row pad (rows=128)
#define GPB 68    // B row pad (cols=64)

__global__ __launch_bounds__(256, 2) void qkv_gemm(const float* __restrict__ x,
                                                   const float* __restrict__ w,
                                                   const float* __restrict__ bias) {
    __shared__ float Ahi[16 * GPA];
    __shared__ float Alo[16 * GPA];
    __shared__ float Bhi[16 * GPB];
    __shared__ float Blo[16 * GPB];

    const int tid  = threadIdx.x;
    const int lane = tid & 31;
    const int wm   = tid >> 5;         // 0..7 (M warp)
    const int g    = lane >> 2;        // 0..7
    const int c    = lane & 3;         // 0..3
    const int m0   = blockIdx.y * 128;
    const int e0   = blockIdx.x * 64;

    // Per-thread load coords
    const int arow0 = tid >> 2;            // 0..63
    const int arow1 = (tid + 256) >> 2;    // 64..127
    const int ac4   = (tid & 3) * 4;
    const int brow  = tid >> 2;            // 0..63
    const int bc4   = ac4;

    const float* xa0 = x + (size_t)(m0 + arow0) * cK + ac4;
    const float* xa1 = x + (size_t)(m0 + arow1) * cK + ac4;
    const float* wb0 = w + (size_t)(e0 + brow) * cK + bc4;

    float acc[8][4];
#pragma unroll
    for (int nt = 0; nt < 8; nt++)
#pragma unroll
        for (int i = 0; i < 4; i++) acc[nt][i] = 0.f;

    // Prefetch tile 0
    float4 pa0 = *(const float4*)(xa0);
    float4 pa1 = *(const float4*)(xa1);
    float4 pb0 = *(const float4*)(wb0);

    for (int kt = 0; kt < cK; kt += 16) {
        __syncthreads();   // previous-iter readers done
        {
            float va0[4] = {pa0.x, pa0.y, pa0.z, pa0.w};
            float va1[4] = {pa1.x, pa1.y, pa1.z, pa1.w};
            float vb0[4] = {pb0.x, pb0.y, pb0.z, pb0.w};
#pragma unroll
            for (int i = 0; i < 4; i++) {
                unsigned hb = f2tf32(va0[i]);
                Ahi[(ac4 + i) * GPA + arow0] = __uint_as_float(hb);
                Alo[(ac4 + i) * GPA + arow0] =
                    __uint_as_float(f2tf32(va0[i] - __uint_as_float(hb)));
                hb = f2tf32(va1[i]);
                Ahi[(ac4 + i) * GPA + arow1] = __uint_as_float(hb);
                Alo[(ac4 + i) * GPA + arow1] =
                    __uint_as_float(f2tf32(va1[i] - __uint_as_float(hb)));
                hb = f2tf32(vb0[i]);
                Bhi[(bc4 + i) * GPB + brow] = __uint_as_float(hb);
                Blo[(bc4 + i) * GPB + brow] =
                    __uint_as_float(f2tf32(vb0[i] - __uint_as_float(hb)));
            }
        }
        __syncthreads();

        // Prefetch next tile (hidden under the mma block)
        if (kt + 16 < cK) {
            pa0 = *(const float4*)(xa0 + kt + 16);
            pa1 = *(const float4*)(xa1 + kt + 16);
            pb0 = *(const float4*)(wb0 + kt + 16);
        }

#pragma unroll
        for (int kc = 0; kc < 2; kc++) {
            const int kb = kc * 8;
            const int r = wm * 16 + g;
            unsigned ah[4], al[4];
            ah[0] = __float_as_uint(Ahi[(kb + c) * GPA + r]);
            ah[1] = __float_as_uint(Ahi[(kb + c) * GPA + r + 8]);
            ah[2] = __float_as_uint(Ahi[(kb + c + 4) * GPA + r]);
            ah[3] = __float_as_uint(Ahi[(kb + c + 4) * GPA + r + 8]);
            al[0] = __float_as_uint(Alo[(kb + c) * GPA + r]);
            al[1] = __float_as_uint(Alo[(kb + c) * GPA + r + 8]);
            al[2] = __float_as_uint(Alo[(kb + c + 4) * GPA + r]);
            al[3] = __float_as_uint(Alo[(kb + c + 4) * GPA + r + 8]);
#pragma unroll
            for (int nt = 0; nt < 8; nt++) {
                int nn = nt * 8 + g;
                unsigned bh0 = __float_as_uint(Bhi[(kb + c) * GPB + nn]);
                unsigned bh1 = __float_as_uint(Bhi[(kb + c + 4) * GPB + nn]);
                unsigned bl0 = __float_as_uint(Blo[(kb + c) * GPB + nn]);
                unsigned bl1 = __float_as_uint(Blo[(kb + c + 4) * GPB + nn]);
                mma_tf32(acc[nt], ah, bh0, bh1);
                mma_tf32(acc[nt], ah, bl0, bl1);
                mma_tf32(acc[nt], al, bh0, bh1);
            }
        }
    }

    // Epilogue: bias + scatter into q/k/v [B,H,N,D].
    // c-frag: c0=(g,2c) c1=(g,2c+1) c2=(g+8,2c) c3=(g+8,2c+1)
#pragma unroll
    for (int hr = 0; hr < 2; hr++) {
        int m  = m0 + wm * 16 + g + hr * 8;
        int bb = m >> 11;
        int n  = m & (cN - 1);
#pragma unroll
        for (int nt = 0; nt < 8; nt++) {
#pragma unroll
            for (int cc = 0; cc < 2; cc++) {
                int e = e0 + nt * 8 + 2 * c + cc;
                float v = acc[nt][hr * 2 + cc] + __ldg(bias + e);
                int h   = e / 192;
                int rem = e - h * 192;
                int d   = rem / 3;
                int jj  = rem - d * 3;
                size_t idx = ((size_t)(bb * cH + h) * cN + n) * cD + d;
                if (jj == 0)      g_q[idx] = v;
                else if (jj == 1) g_k[idx] = v;
                else              g_v[idx] = v;
            }
        }
    }
}

// ---------------------------------------------------------------------------
// Kernel 2: in-place RMS-norm over head dim for q (blockIdx.y=0) and k (=1).
// ---------------------------------------------------------------------------
__global__ __launch_bounds__(256) void rmsnorm(const float* __restrict__ qw,
                                               const float* __restrict__ kw) {
    int warp = threadIdx.x >> 5;
    int lane = threadIdx.x & 31;
    size_t row = (size_t)blockIdx.x * 8 + warp;     // < B*H*N = 65536
    float* base = blockIdx.y ? g_k : g_q;
    const float* wv = blockIdx.y ? kw : qw;

    float2 v = *(float2*)(base + row * cD + lane * 2);
    float ss = v.x * v.x + v.y * v.y;
#pragma unroll
    for (int o = 16; o > 0; o >>= 1) ss += __shfl_xor_sync(0xffffffffu, ss, o);
    float inv = rsqrtf(ss * (1.0f / cD) + 1e-6f);
    float2 g = *(const float2*)(wv + lane * 2);
    v.x *= inv * g.x;
    v.y *= inv * g.y;
    *(float2*)(base + row * cD + lane * 2) = v;
}

// ---------------------------------------------------------------------------
// Kernel 3: attention, flash-style WITHOUT online max (|score| <= 8 exactly:
// RMS norm fixes ||q||=||k||=8, scale=0.125). 128-row Q tile, 64-key tiles,
// 256 threads, 8x4 per thread, scalar FFMA (proven R4 version, ~855us).
// Smem (dynamic, 96KB): Qs[128][64], Ks[64][64] ([d][c]), Vs[64][64],
// Ps[128][64]. 3 syncs per key tile.
// ---------------------------------------------------------------------------
__global__ __launch_bounds__(256, 2) void attn(float* __restrict__ out) {
    extern __shared__ float sm[];
    float* Qs = sm;                 // [128][64]
    float* Ks = sm + 8192;          // [64][64]  (K transposed: [d][c])
    float* Vs = sm + 12288;         // [64][64]  ([c][d])
    float* Ps = sm + 16384;         // [128][64]

    const int tid = threadIdx.x;
    const int tx = tid & 15;
    const int ty = tid >> 4;
    const int bh = blockIdx.y;             // 0..31  (b*H + h)
    const int q0 = blockIdx.x * 128;
    const float* qb = g_q + (size_t)bh * cN * cD;
    const float* kb = g_k + (size_t)bh * cN * cD;
    const float* vb = g_v + (size_t)bh * cN * cD;

#pragma unroll
    for (int p = 0; p < 8; p++) {
        int l  = tid + p * 256;
        int r  = l >> 4;
        int c4 = (l & 15) * 4;
        *(float4*)&Qs[r * 64 + c4] = *(const float4*)(qb + (size_t)(q0 + r) * cD + c4);
    }

    float o[8][4];
    float lsum[8];
#pragma unroll
    for (int i = 0; i < 8; i++) {
        lsum[i] = 0.f;
#pragma unroll
        for (int j = 0; j < 4; j++) o[i][j] = 0.f;
    }

    for (int kt = 0; kt < cN; kt += 64) {
        __syncthreads();   // prev-iter Ps/Vs readers done (covers Q load iter 0)

        // K tile transposed: Ks[d][c] = k[kt+c][d]
#pragma unroll
        for (int p = 0; p < 4; p++) {
            int l  = tid + p * 256;
            int c  = l & 63;
            int d4 = (l >> 6) * 4;
            float4 t = *(const float4*)(kb + (size_t)(kt + c) * cD + d4);
            Ks[(d4 + 0) * 64 + c] = t.x;
            Ks[(d4 + 1) * 64 + c] = t.y;
            Ks[(d4 + 2) * 64 + c] = t.z;
            Ks[(d4 + 3) * 64 + c] = t.w;
        }
        // V tile row-major: Vs[c][d]
#pragma unroll
        for (int p = 0; p < 4; p++) {
            int l  = tid + p * 256;
            int r  = l >> 4;
            int c4 = (l & 15) * 4;
            *(float4*)&Vs[r * 64 + c4] = *(const float4*)(vb + (size_t)(kt + r) * cD + c4);
        }
        __syncthreads();

        // S = Q K^T  (8x4 per thread)
        float s[8][4];
#pragma unroll
        for (int i = 0; i < 8; i++)
#pragma unroll
            for (int j = 0; j < 4; j++) s[i][j] = 0.f;

#pragma unroll
        for (int d4 = 0; d4 < 64; d4 += 4) {
            float qf[8][4], kf[4][4];
#pragma unroll
            for (int i = 0; i < 8; i++) {
                float4 t = *(const float4*)&Qs[(ty * 8 + i) * 64 + d4];
                qf[i][0] = t.x; qf[i][1] = t.y; qf[i][2] = t.z; qf[i][3] = t.w;
            }
#pragma unroll
            for (int dd = 0; dd < 4; dd++) {
                float4 t = *(const float4*)&Ks[(d4 + dd) * 64 + tx * 4];
                kf[dd][0] = t.x; kf[dd][1] = t.y; kf[dd][2] = t.z; kf[dd][3] = t.w;
            }
#pragma unroll
            for (int i = 0; i < 8; i++)
#pragma unroll
                for (int j = 0; j < 4; j++)
#pragma unroll
                    for (int dd = 0; dd < 4; dd++)
                        s[i][j] += qf[i][dd] * kf[dd][j];
        }

        // P = exp(S * scale); row-sum partials; stage P in smem
#pragma unroll
        for (int i = 0; i < 8; i++) {
            float4 pv;
            pv.x = __expf(s[i][0] * 0.125f);
            pv.y = __expf(s[i][1] * 0.125f);
            pv.z = __expf(s[i][2] * 0.125f);
            pv.w = __expf(s[i][3] * 0.125f);
            lsum[i] += pv.x + pv.y + pv.z + pv.w;
            *(float4*)&Ps[(ty * 8 + i) * 64 + tx * 4] = pv;
        }
        __syncthreads();

        // O += P * V
#pragma unroll
        for (int c4 = 0; c4 < 64; c4 += 4) {
            float pf[8][4], vf[4][4];
#pragma unroll
            for (int i = 0; i < 8; i++) {
                float4 t = *(const float4*)&Ps[(ty * 8 + i) * 64 + c4];
                pf[i][0] = t.x; pf[i][1] = t.y; pf[i][2] = t.z; pf[i][3] = t.w;
            }
#pragma unroll
            for (int cc = 0; cc < 4; cc++) {
                float4 t = *(const float4*)&Vs[(c4 + cc) * 64 + tx * 4];
                vf[cc][0] = t.x; vf[cc][1] = t.y; vf[cc][2] = t.z; vf[cc][3] = t.w;
            }
#pragma unroll
            for (int i = 0; i < 8; i++)
#pragma unroll
                for (int j = 0; j < 4; j++)
#pragma unroll
                    for (int cc = 0; cc < 4; cc++)
                        o[i][j] += pf[i][cc] * vf[cc][j];
        }
    }

    // Reduce row sums across the 16 tx lanes
#pragma unroll
    for (int i = 0; i < 8; i++) {
#pragma unroll
        for (int off = 1; off < 16; off <<= 1)
            lsum[i] += __shfl_xor_sync(0xffffffffu, lsum[i], off);
    }

    // Write out: out[b][n][h*64 + d]
    int bb = bh >> 4;
    int h  = bh & 15;
#pragma unroll
    for (int i = 0; i < 8; i++) {
        int n = q0 + ty * 8 + i;
        float inv = 1.0f / lsum[i];
        float4 r4;
        r4.x = o[i][0] * inv;
        r4.y = o[i][1] * inv;
        r4.z = o[i][2] * inv;
        r4.w = o[i][3] * inv;
        *(float4*)(out + ((size_t)(bb * cN + n)) * cDIM + h * cD + tx * 4) = r4;
    }
}

// ---------------------------------------------------------------------------
extern "C" void kernel_launch(void* const* d_in, const int* in_sizes, int n_in,
                              void* d_out, int out_size) {
    const float* x        = (const float*)d_in[0];
    const float* qkv_w    = (const float*)d_in[1];
    const float* qkv_b    = (const float*)d_in[2];
    const float* q_norm_w = (const float*)d_in[3];
    const float* k_norm_w = (const float*)d_in[4];
    float* out = (float*)d_out;

    // Idempotent, not a stream op (graph-capture safe); no static guard.
    cudaFuncSetAttribute(attn, cudaFuncAttributeMaxDynamicSharedMemorySize,
                         96 * 1024);

    dim3 g1(cE / 64, cM / 128);          // 48 x 32
    qkv_gemm<<<g1, 256>>>(x, qkv_w, qkv_b);

    dim3 g2((cB * cH * cN) / 8, 2);      // 8192 x 2
    rmsnorm<<<g2, 256>>>(q_norm_w, k_norm_w);

    dim3 g3(cN / 128, cB * cH);          // 16 x 32
    attn<<<g3, 256, 96 * 1024>>>(out);
}

// round 15
// speedup vs baseline: 1.2266x; 1.2266x over previous
#include <cuda_runtime.h>

#define cB 2
#define cN 2048
#define cDIM 1024
#define cH 16
#define cD 64
#define cE 3072      // 3*DIM
#define cM 4096      // B*N
#define cK 1024

// Scratch: q,k,v in [B,H,N,D] layout (16 MB each)
__device__ float g_q[cB * cH * cN * cD];
__device__ float g_k[cB * cH * cN * cD];
__device__ float g_v[cB * cH * cN * cD];

// ---- tf32 helpers ----------------------------------------------------------
__device__ __forceinline__ unsigned f2tf32(float x) {
    unsigned r;
    asm("cvt.rna.tf32.f32 %0, %1;" : "=r"(r) : "f"(x));
    return r;
}
// D += A * B  (m16n8k8 tf32)
__device__ __forceinline__ void mma_tf32(float* cc, const unsigned* a,
                                         unsigned b0, unsigned b1) {
    asm volatile(
        "mma.sync.aligned.m16n8k8.row.col.f32.tf32.tf32.f32 "
        "{%0,%1,%2,%3}, {%4,%5,%6,%7}, {%8,%9}, {%0,%1,%2,%3};"
        : "+f"(cc[0]), "+f"(cc[1]), "+f"(cc[2]), "+f"(cc[3])
        : "r"(a[0]), "r"(a[1]), "r"(a[2]), "r"(a[3]), "r"(b0), "r"(b1));
}

// ---------------------------------------------------------------------------
// Kernel 1: qkv = x @ W^T + b via split-tf32 mma with fragment-plane smem.
// CTA 128m x 128e, BK=16, 256 threads = 8 warps (2m x 4n), warp tile 64x32.
// Smem holds fragments in SoA planes (one plane per mma fragment register):
//   A: 8 planes (hi j0..3, lo j0..3), block = (kc*8+mb)*33 words, word=c*8+g
//   B: 4 planes (b0h,b1h,b0l,b1l),    block = (kc*16+ntg)*33,     word=g+8*c
// Plane strides 552 / 1064 stagger bases by 8 words mod 32 -> conflict-free
// STS scatter AND conflict-free scalar-LDS fragment reads.
// 3-term split tf32: D += Ahi*Bhi + Ahi*Blo + Alo*Bhi (~2^-22 rel error).
// ---------------------------------------------------------------------------
#define APL 552    // A plane stride (>= 528 = 16 blocks * 33), 552 % 32 == 8
#define BPL 1064   // B plane stride (>= 1056 = 32 blocks * 33), 1064 % 32 == 8

__global__ __launch_bounds__(256, 2) void qkv_gemm(const float* __restrict__ x,
                                                   const float* __restrict__ wgt,
                                                   const float* __restrict__ bias) {
    __shared__ float Ap[8 * APL];   // 17.3 KB
    __shared__ float Bp[4 * BPL];   // 17.0 KB

    const int tid  = threadIdx.x;
    const int lane = tid & 31;
    const int wrp  = tid >> 5;
    const int wm   = wrp >> 2;         // 0..1 (M)
    const int wn   = wrp & 3;          // 0..3 (N)
    const int g    = lane >> 2;        // 0..7
    const int c    = lane & 3;         // 0..3
    const int m0   = blockIdx.y * 128;
    const int e0   = blockIdx.x * 128;

    // Loader coords: thread handles rows lr and lr+64, k-quad lc4..lc4+3
    const int lr  = tid >> 2;          // 0..63
    const int lc4 = (tid & 3) * 4;     // 0,4,8,12
    const float* xp = x   + (size_t)(m0 + lr) * cK + lc4;
    const float* wp = wgt + (size_t)(e0 + lr) * cK + lc4;

    float acc[4][4][4];
#pragma unroll
    for (int mb = 0; mb < 4; mb++)
#pragma unroll
        for (int nt = 0; nt < 4; nt++)
#pragma unroll
            for (int i = 0; i < 4; i++) acc[mb][nt][i] = 0.f;

    float4 pa0 = *(const float4*)(xp);
    float4 pa1 = *(const float4*)(xp + (size_t)64 * cK);
    float4 pb0 = *(const float4*)(wp);
    float4 pb1 = *(const float4*)(wp + (size_t)64 * cK);

    // Per-float4 constant pieces: kc = lc4>>3, kh = (lc4&7)>>2
    const int skc = lc4 >> 3;
    const int skh = (lc4 & 7) >> 2;

    for (int kt = 0; kt < cK; kt += 16) {
        __syncthreads();   // previous-iter fragment readers done
        {
            // ---- A rows lr and lr+64 ----
            float va[2][4] = {{pa0.x, pa0.y, pa0.z, pa0.w},
                              {pa1.x, pa1.y, pa1.z, pa1.w}};
#pragma unroll
            for (int rep = 0; rep < 2; rep++) {
                int row = lr + rep * 64;
                int mb  = row >> 4;
                int h   = (row >> 3) & 1;
                int gg  = row & 7;
                int j   = h + 2 * skh;
                int wb  = (skc * 8 + mb) * 33 + gg;   // + 8*i per element
#pragma unroll
                for (int i = 0; i < 4; i++) {
                    unsigned hb = f2tf32(va[rep][i]);
                    unsigned lb = f2tf32(va[rep][i] - __uint_as_float(hb));
                    Ap[j * APL + wb + 8 * i]       = __uint_as_float(hb);
                    Ap[(4 + j) * APL + wb + 8 * i] = __uint_as_float(lb);
                }
            }
            // ---- B rows lr and lr+64 ----
            float vb[2][4] = {{pb0.x, pb0.y, pb0.z, pb0.w},
                              {pb1.x, pb1.y, pb1.z, pb1.w}};
#pragma unroll
            for (int rep = 0; rep < 2; rep++) {
                int n   = lr + rep * 64;
                int ntg = n >> 3;
                int gg  = n & 7;
                int pl  = skh;                        // b0 or b1 plane
                int wb  = (skc * 16 + ntg) * 33 + gg; // + 8*i per element
#pragma unroll
                for (int i = 0; i < 4; i++) {
                    unsigned hb = f2tf32(vb[rep][i]);
                    unsigned lb = f2tf32(vb[rep][i] - __uint_as_float(hb));
                    Bp[pl * BPL + wb + 8 * i]       = __uint_as_float(hb);
                    Bp[(2 + pl) * BPL + wb + 8 * i] = __uint_as_float(lb);
                }
            }
        }
        __syncthreads();

        if (kt + 16 < cK) {
            pa0 = *(const float4*)(xp + kt + 16);
            pa1 = *(const float4*)(xp + (size_t)64 * cK + kt + 16);
            pb0 = *(const float4*)(wp + kt + 16);
            pb1 = *(const float4*)(wp + (size_t)64 * cK + kt + 16);
        }

#pragma unroll
        for (int kc = 0; kc < 2; kc++) {
            // B fragments for this warp's 4 n-tiles
            unsigned bh0[4], bh1[4], bl0[4], bl1[4];
#pragma unroll
            for (int nt = 0; nt < 4; nt++) {
                int off = (kc * 16 + wn * 4 + nt) * 33 + g + 8 * c;
                bh0[nt] = __float_as_uint(Bp[off]);
                bh1[nt] = __float_as_uint(Bp[BPL + off]);
                bl0[nt] = __float_as_uint(Bp[2 * BPL + off]);
                bl1[nt] = __float_as_uint(Bp[3 * BPL + off]);
            }
#pragma unroll
            for (int mb = 0; mb < 4; mb++) {
                int aoff = (kc * 8 + wm * 4 + mb) * 33 + c * 8 + g;
                unsigned ah[4], al[4];
#pragma unroll
                for (int j = 0; j < 4; j++) {
                    ah[j] = __float_as_uint(Ap[j * APL + aoff]);
                    al[j] = __float_as_uint(Ap[(4 + j) * APL + aoff]);
                }
#pragma unroll
                for (int nt = 0; nt < 4; nt++) {
                    mma_tf32(acc[mb][nt], ah, bh0[nt], bh1[nt]);
                    mma_tf32(acc[mb][nt], ah, bl0[nt], bl1[nt]);
                    mma_tf32(acc[mb][nt], al, bh0[nt], bh1[nt]);
                }
            }
        }
    }

    // Epilogue: bias + scatter into q/k/v [B,H,N,D].
    // c-frag: c0=(g,2c) c1=(g,2c+1) c2=(g+8,2c) c3=(g+8,2c+1)
#pragma unroll
    for (int mb = 0; mb < 4; mb++) {
#pragma unroll
        for (int hr = 0; hr < 2; hr++) {
            int m  = m0 + wm * 64 + mb * 16 + g + hr * 8;
            int bb = m >> 11;
            int n  = m & (cN - 1);
#pragma unroll
            for (int nt = 0; nt < 4; nt++) {
#pragma unroll
                for (int cc = 0; cc < 2; cc++) {
                    int e = e0 + wn * 32 + nt * 8 + 2 * c + cc;
                    float v = acc[mb][nt][hr * 2 + cc] + __ldg(bias + e);
                    int h   = e / 192;
                    int rem = e - h * 192;
                    int d   = rem / 3;
                    int jj  = rem - d * 3;
                    size_t idx = ((size_t)(bb * cH + h) * cN + n) * cD + d;
                    if (jj == 0)      g_q[idx] = v;
                    else if (jj == 1) g_k[idx] = v;
                    else              g_v[idx] = v;
                }
            }
        }
    }
}

// ---------------------------------------------------------------------------
// Kernel 2: in-place RMS-norm over head dim for q (blockIdx.y=0) and k (=1).
// ---------------------------------------------------------------------------
__global__ __launch_bounds__(256) void rmsnorm(const float* __restrict__ qw,
                                               const float* __restrict__ kw) {
    int warp = threadIdx.x >> 5;
    int lane = threadIdx.x & 31;
    size_t row = (size_t)blockIdx.x * 8 + warp;     // < B*H*N = 65536
    float* base = blockIdx.y ? g_k : g_q;
    const float* wv = blockIdx.y ? kw : qw;

    float2 v = *(float2*)(base + row * cD + lane * 2);
    float ss = v.x * v.x + v.y * v.y;
#pragma unroll
    for (int o = 16; o > 0; o >>= 1) ss += __shfl_xor_sync(0xffffffffu, ss, o);
    float inv = rsqrtf(ss * (1.0f / cD) + 1e-6f);
    float2 g = *(const float2*)(wv + lane * 2);
    v.x *= inv * g.x;
    v.y *= inv * g.y;
    *(float2*)(base + row * cD + lane * 2) = v;
}

// ---------------------------------------------------------------------------
// Kernel 3: attention, flash-style WITHOUT online max (|score| <= 8 exactly:
// RMS norm fixes ||q||=||k||=8, scale=0.125). 128-row Q tile, 64-key tiles,
// 256 threads, 8x4 per thread, scalar FFMA (proven R4 version, ~830us).
// Smem (dynamic, 96KB): Qs[128][64], Ks[64][64] ([d][c]), Vs[64][64],
// Ps[128][64]. 3 syncs per key tile.
// ---------------------------------------------------------------------------
__global__ __launch_bounds__(256, 2) void attn(float* __restrict__ out) {
    extern __shared__ float sm[];
    float* Qs = sm;                 // [128][64]
    float* Ks = sm + 8192;          // [64][64]  (K transposed: [d][c])
    float* Vs = sm + 12288;         // [64][64]  ([c][d])
    float* Ps = sm + 16384;         // [128][64]

    const int tid = threadIdx.x;
    const int tx = tid & 15;
    const int ty = tid >> 4;
    const int bh = blockIdx.y;             // 0..31  (b*H + h)
    const int q0 = blockIdx.x * 128;
    const float* qb = g_q + (size_t)bh * cN * cD;
    const float* kb = g_k + (size_t)bh * cN * cD;
    const float* vb = g_v + (size_t)bh * cN * cD;

#pragma unroll
    for (int p = 0; p < 8; p++) {
        int l  = tid + p * 256;
        int r  = l >> 4;
        int c4 = (l & 15) * 4;
        *(float4*)&Qs[r * 64 + c4] = *(const float4*)(qb + (size_t)(q0 + r) * cD + c4);
    }

    float o[8][4];
    float lsum[8];
#pragma unroll
    for (int i = 0; i < 8; i++) {
        lsum[i] = 0.f;
#pragma unroll
        for (int j = 0; j < 4; j++) o[i][j] = 0.f;
    }

    for (int kt = 0; kt < cN; kt += 64) {
        __syncthreads();   // prev-iter Ps/Vs readers done (covers Q load iter 0)

        // K tile transposed: Ks[d][c] = k[kt+c][d]
#pragma unroll
        for (int p = 0; p < 4; p++) {
            int l  = tid + p * 256;
            int c  = l & 63;
            int d4 = (l >> 6) * 4;
            float4 t = *(const float4*)(kb + (size_t)(kt + c) * cD + d4);
            Ks[(d4 + 0) * 64 + c] = t.x;
            Ks[(d4 + 1) * 64 + c] = t.y;
            Ks[(d4 + 2) * 64 + c] = t.z;
            Ks[(d4 + 3) * 64 + c] = t.w;
        }
        // V tile row-major: Vs[c][d]
#pragma unroll
        for (int p = 0; p < 4; p++) {
            int l  = tid + p * 256;
            int r  = l >> 4;
            int c4 = (l & 15) * 4;
            *(float4*)&Vs[r * 64 + c4] = *(const float4*)(vb + (size_t)(kt + r) * cD + c4);
        }
        __syncthreads();

        // S = Q K^T  (8x4 per thread)
        float s[8][4];
#pragma unroll
        for (int i = 0; i < 8; i++)
#pragma unroll
            for (int j = 0; j < 4; j++) s[i][j] = 0.f;

#pragma unroll
        for (int d4 = 0; d4 < 64; d4 += 4) {
            float qf[8][4], kf[4][4];
#pragma unroll
            for (int i = 0; i < 8; i++) {
                float4 t = *(const float4*)&Qs[(ty * 8 + i) * 64 + d4];
                qf[i][0] = t.x; qf[i][1] = t.y; qf[i][2] = t.z; qf[i][3] = t.w;
            }
#pragma unroll
            for (int dd = 0; dd < 4; dd++) {
                float4 t = *(const float4*)&Ks[(d4 + dd) * 64 + tx * 4];
                kf[dd][0] = t.x; kf[dd][1] = t.y; kf[dd][2] = t.z; kf[dd][3] = t.w;
            }
#pragma unroll
            for (int i = 0; i < 8; i++)
#pragma unroll
                for (int j = 0; j < 4; j++)
#pragma unroll
                    for (int dd = 0; dd < 4; dd++)
                        s[i][j] += qf[i][dd] * kf[dd][j];
        }

        // P = exp(S * scale); row-sum partials; stage P in smem
#pragma unroll
        for (int i = 0; i < 8; i++) {
            float4 pv;
            pv.x = __expf(s[i][0] * 0.125f);
            pv.y = __expf(s[i][1] * 0.125f);
            pv.z = __expf(s[i][2] * 0.125f);
            pv.w = __expf(s[i][3] * 0.125f);
            lsum[i] += pv.x + pv.y + pv.z + pv.w;
            *(float4*)&Ps[(ty * 8 + i) * 64 + tx * 4] = pv;
        }
        __syncthreads();

        // O += P * V
#pragma unroll
        for (int c4 = 0; c4 < 64; c4 += 4) {
            float pf[8][4], vf[4][4];
#pragma unroll
            for (int i = 0; i < 8; i++) {
                float4 t = *(const float4*)&Ps[(ty * 8 + i) * 64 + c4];
                pf[i][0] = t.x; pf[i][1] = t.y; pf[i][2] = t.z; pf[i][3] = t.w;
            }
#pragma unroll
            for (int cc = 0; cc < 4; cc++) {
                float4 t = *(const float4*)&Vs[(c4 + cc) * 64 + tx * 4];
                vf[cc][0] = t.x; vf[cc][1] = t.y; vf[cc][2] = t.z; vf[cc][3] = t.w;
            }
#pragma unroll
            for (int i = 0; i < 8; i++)
#pragma unroll
                for (int j = 0; j < 4; j++)
#pragma unroll
                    for (int cc = 0; cc < 4; cc++)
                        o[i][j] += pf[i][cc] * vf[cc][j];
        }
    }

    // Reduce row sums across the 16 tx lanes
#pragma unroll
    for (int i = 0; i < 8; i++) {
#pragma unroll
        for (int off = 1; off < 16; off <<= 1)
            lsum[i] += __shfl_xor_sync(0xffffffffu, lsum[i], off);
    }

    // Write out: out[b][n][h*64 + d]
    int bb = bh >> 4;
    int h  = bh & 15;
#pragma unroll
    for (int i = 0; i < 8; i++) {
        int n = q0 + ty * 8 + i;
        float inv = 1.0f / lsum[i];
        float4 r4;
        r4.x = o[i][0] * inv;
        r4.y = o[i][1] * inv;
        r4.z = o[i][2] * inv;
        r4.w = o[i][3] * inv;
        *(float4*)(out + ((size_t)(bb * cN + n)) * cDIM + h * cD + tx * 4) = r4;
    }
}

// ---------------------------------------------------------------------------
extern "C" void kernel_launch(void* const* d_in, const int* in_sizes, int n_in,
                              void* d_out, int out_size) {
    const float* x        = (const float*)d_in[0];
    const float* qkv_w    = (const float*)d_in[1];
    const float* qkv_b    = (const float*)d_in[2];
    const float* q_norm_w = (const float*)d_in[3];
    const float* k_norm_w = (const float*)d_in[4];
    float* out = (float*)d_out;

    // Idempotent, not a stream op (graph-capture safe); no static guard.
    cudaFuncSetAttribute(attn, cudaFuncAttributeMaxDynamicSharedMemorySize,
                         96 * 1024);

    dim3 g1(cE / 128, cM / 128);         // 24 x 32
    qkv_gemm<<<g1, 256>>>(x, qkv_w, qkv_b);

    dim3 g2((cB * cH * cN) / 8, 2);      // 8192 x 2
    rmsnorm<<<g2, 256>>>(q_norm_w, k_norm_w);

    dim3 g3(cN / 128, cB * cH);          // 16 x 32
    attn<<<g3, 256, 96 * 1024>>>(out);
}

// round 16
// speedup vs baseline: 1.6025x; 1.3064x over previous
#include <cuda_runtime.h>

#define cB 2
#define cN 2048
#define cDIM 1024
#define cH 16
#define cD 64
#define cE 3072      // 3*DIM
#define cM 4096      // B*N
#define cK 1024

// Scratch: q,k,v in [B,H,N,D] layout (16 MB each)
__device__ float g_q[cB * cH * cN * cD];
__device__ float g_k[cB * cH * cN * cD];
__device__ float g_v[cB * cH * cN * cD];

// ---- tf32 helpers ----------------------------------------------------------
__device__ __forceinline__ unsigned f2tf32(float x) {
    unsigned r;
    asm("cvt.rna.tf32.f32 %0, %1;" : "=r"(r) : "f"(x));
    return r;
}
// D += A * B  (m16n8k8 tf32)
__device__ __forceinline__ void mma_tf32(float* cc, const unsigned* a,
                                         unsigned b0, unsigned b1) {
    asm volatile(
        "mma.sync.aligned.m16n8k8.row.col.f32.tf32.tf32.f32 "
        "{%0,%1,%2,%3}, {%4,%5,%6,%7}, {%8,%9}, {%0,%1,%2,%3};"
        : "+f"(cc[0]), "+f"(cc[1]), "+f"(cc[2]), "+f"(cc[3])
        : "r"(a[0]), "r"(a[1]), "r"(a[2]), "r"(a[3]), "r"(b0), "r"(b1));
}

// ---------------------------------------------------------------------------
// Kernel 1: qkv = x @ W^T + b via split-tf32 mma with fragment-plane smem.
// (unchanged from R15: 466us, tensor 54%)
// ---------------------------------------------------------------------------
#define APL 552    // A plane stride (>= 528 = 16 blocks * 33), 552 % 32 == 8
#define BPL 1064   // B plane stride (>= 1056 = 32 blocks * 33), 1064 % 32 == 8

__global__ __launch_bounds__(256, 2) void qkv_gemm(const float* __restrict__ x,
                                                   const float* __restrict__ wgt,
                                                   const float* __restrict__ bias) {
    __shared__ float Ap[8 * APL];
    __shared__ float Bp[4 * BPL];

    const int tid  = threadIdx.x;
    const int lane = tid & 31;
    const int wrp  = tid >> 5;
    const int wm   = wrp >> 2;
    const int wn   = wrp & 3;
    const int g    = lane >> 2;
    const int c    = lane & 3;
    const int m0   = blockIdx.y * 128;
    const int e0   = blockIdx.x * 128;

    const int lr  = tid >> 2;
    const int lc4 = (tid & 3) * 4;
    const float* xp = x   + (size_t)(m0 + lr) * cK + lc4;
    const float* wp = wgt + (size_t)(e0 + lr) * cK + lc4;

    float acc[4][4][4];
#pragma unroll
    for (int mb = 0; mb < 4; mb++)
#pragma unroll
        for (int nt = 0; nt < 4; nt++)
#pragma unroll
            for (int i = 0; i < 4; i++) acc[mb][nt][i] = 0.f;

    float4 pa0 = *(const float4*)(xp);
    float4 pa1 = *(const float4*)(xp + (size_t)64 * cK);
    float4 pb0 = *(const float4*)(wp);
    float4 pb1 = *(const float4*)(wp + (size_t)64 * cK);

    const int skc = lc4 >> 3;
    const int skh = (lc4 & 7) >> 2;

    for (int kt = 0; kt < cK; kt += 16) {
        __syncthreads();
        {
            float va[2][4] = {{pa0.x, pa0.y, pa0.z, pa0.w},
                              {pa1.x, pa1.y, pa1.z, pa1.w}};
#pragma unroll
            for (int rep = 0; rep < 2; rep++) {
                int row = lr + rep * 64;
                int mb  = row >> 4;
                int h   = (row >> 3) & 1;
                int gg  = row & 7;
                int j   = h + 2 * skh;
                int wb  = (skc * 8 + mb) * 33 + gg;
#pragma unroll
                for (int i = 0; i < 4; i++) {
                    unsigned hb = f2tf32(va[rep][i]);
                    unsigned lb = f2tf32(va[rep][i] - __uint_as_float(hb));
                    Ap[j * APL + wb + 8 * i]       = __uint_as_float(hb);
                    Ap[(4 + j) * APL + wb + 8 * i] = __uint_as_float(lb);
                }
            }
            float vb[2][4] = {{pb0.x, pb0.y, pb0.z, pb0.w},
                              {pb1.x, pb1.y, pb1.z, pb1.w}};
#pragma unroll
            for (int rep = 0; rep < 2; rep++) {
                int n   = lr + rep * 64;
                int ntg = n >> 3;
                int gg  = n & 7;
                int pl  = skh;
                int wb  = (skc * 16 + ntg) * 33 + gg;
#pragma unroll
                for (int i = 0; i < 4; i++) {
                    unsigned hb = f2tf32(vb[rep][i]);
                    unsigned lb = f2tf32(vb[rep][i] - __uint_as_float(hb));
                    Bp[pl * BPL + wb + 8 * i]       = __uint_as_float(hb);
                    Bp[(2 + pl) * BPL + wb + 8 * i] = __uint_as_float(lb);
                }
            }
        }
        __syncthreads();

        if (kt + 16 < cK) {
            pa0 = *(const float4*)(xp + kt + 16);
            pa1 = *(const float4*)(xp + (size_t)64 * cK + kt + 16);
            pb0 = *(const float4*)(wp + kt + 16);
            pb1 = *(const float4*)(wp + (size_t)64 * cK + kt + 16);
        }

#pragma unroll
        for (int kc = 0; kc < 2; kc++) {
            unsigned bh0[4], bh1[4], bl0[4], bl1[4];
#pragma unroll
            for (int nt = 0; nt < 4; nt++) {
                int off = (kc * 16 + wn * 4 + nt) * 33 + g + 8 * c;
                bh0[nt] = __float_as_uint(Bp[off]);
                bh1[nt] = __float_as_uint(Bp[BPL + off]);
                bl0[nt] = __float_as_uint(Bp[2 * BPL + off]);
                bl1[nt] = __float_as_uint(Bp[3 * BPL + off]);
            }
#pragma unroll
            for (int mb = 0; mb < 4; mb++) {
                int aoff = (kc * 8 + wm * 4 + mb) * 33 + c * 8 + g;
                unsigned ah[4], al[4];
#pragma unroll
                for (int j = 0; j < 4; j++) {
                    ah[j] = __float_as_uint(Ap[j * APL + aoff]);
                    al[j] = __float_as_uint(Ap[(4 + j) * APL + aoff]);
                }
#pragma unroll
                for (int nt = 0; nt < 4; nt++) {
                    mma_tf32(acc[mb][nt], ah, bh0[nt], bh1[nt]);
                    mma_tf32(acc[mb][nt], ah, bl0[nt], bl1[nt]);
                    mma_tf32(acc[mb][nt], al, bh0[nt], bh1[nt]);
                }
            }
        }
    }

#pragma unroll
    for (int mb = 0; mb < 4; mb++) {
#pragma unroll
        for (int hr = 0; hr < 2; hr++) {
            int m  = m0 + wm * 64 + mb * 16 + g + hr * 8;
            int bb = m >> 11;
            int n  = m & (cN - 1);
#pragma unroll
            for (int nt = 0; nt < 4; nt++) {
#pragma unroll
                for (int cc = 0; cc < 2; cc++) {
                    int e = e0 + wn * 32 + nt * 8 + 2 * c + cc;
                    float v = acc[mb][nt][hr * 2 + cc] + __ldg(bias + e);
                    int h   = e / 192;
                    int rem = e - h * 192;
                    int d   = rem / 3;
                    int jj  = rem - d * 3;
                    size_t idx = ((size_t)(bb * cH + h) * cN + n) * cD + d;
                    if (jj == 0)      g_q[idx] = v;
                    else if (jj == 1) g_k[idx] = v;
                    else              g_v[idx] = v;
                }
            }
        }
    }
}

// ---------------------------------------------------------------------------
// Kernel 2: in-place RMS-norm over head dim for q (blockIdx.y=0) and k (=1).
// ---------------------------------------------------------------------------
__global__ __launch_bounds__(256) void rmsnorm(const float* __restrict__ qw,
                                               const float* __restrict__ kw) {
    int warp = threadIdx.x >> 5;
    int lane = threadIdx.x & 31;
    size_t row = (size_t)blockIdx.x * 8 + warp;
    float* base = blockIdx.y ? g_k : g_q;
    const float* wv = blockIdx.y ? kw : qw;

    float2 v = *(float2*)(base + row * cD + lane * 2);
    float ss = v.x * v.x + v.y * v.y;
#pragma unroll
    for (int o = 16; o > 0; o >>= 1) ss += __shfl_xor_sync(0xffffffffu, ss, o);
    float inv = rsqrtf(ss * (1.0f / cD) + 1e-6f);
    float2 g = *(const float2*)(wv + lane * 2);
    v.x *= inv * g.x;
    v.y *= inv * g.y;
    *(float2*)(base + row * cD + lane * 2) = v;
}

// ---------------------------------------------------------------------------
// Kernel 3: attention via split-tf32 mma, flash-style without online max
// (|score| <= 8 exactly after RMS norm; scale 0.125).
// CTA = 64 q-rows, key-tiles of 64, 256 threads = 8 warps (2m x 4n).
// S-phase: Q split hi/lo (3-term, exact); PV: P and V single tf32 (1 term,
// ~3e-4 rel err). Q converted to A-planes ONCE; K/V converted per tile;
// P written as A-planes from S c-frags. lsum from unrounded exp.
// Smem 103KB dynamic -> 2 CTAs/SM.
// ---------------------------------------------------------------------------
#define QPL 1064   // Q A-plane stride (32 blocks*33=1056), 8 planes (hi/lo)
#define KPL 2120   // K B-plane stride (64 blocks*33=2112), 4 planes (hi/lo)
#define PPL 1064   // P A-plane stride (32 blocks*33),      4 planes (single)
#define VPL 2120   // V B-plane stride (64 blocks*33),      2 planes (single)
#define OFF_K 8512
#define OFF_P 16992
#define OFF_V 21248
#define OFF_L 25488
#define ATTN_SMEM_WORDS 25744   // 102976 bytes

__global__ __launch_bounds__(256, 2) void attn(float* __restrict__ out) {
    extern __shared__ float smA[];
    float* Qp = smA;
    float* Kp = smA + OFF_K;
    float* Pp = smA + OFF_P;
    float* Vp = smA + OFF_V;
    float* Ls = smA + OFF_L;   // [4][64] per-nwarp lsum partials

    const int tid  = threadIdx.x;
    const int lane = tid & 31;
    const int wrp  = tid >> 5;
    const int wm   = wrp >> 2;        // 0..1 (q-rows)
    const int wn   = wrp & 3;         // 0..3
    const int g    = lane >> 2;       // 0..7
    const int c    = lane & 3;        // 0..3
    const int bh   = blockIdx.y;      // b*H + h
    const int q0   = blockIdx.x * 64;
    const float* qb = g_q + (size_t)bh * cN * cD;
    const float* kb = g_k + (size_t)bh * cN * cD;
    const float* vb = g_v + (size_t)bh * cN * cD;

    // Loader coords: row = tid>>2 (0..63), 4 k-chunks of 4 across rep
    const int lr  = tid >> 2;
    const int lq4 = (tid & 3) * 4;

    // ---- Convert Q tile (64x64) into A-planes hi/lo, once ----
#pragma unroll
    for (int rep = 0; rep < 4; rep++) {
        int kb4 = lq4 + rep * 16;
        float4 v = *(const float4*)(qb + (size_t)(q0 + lr) * cD + kb4);
        float va[4] = {v.x, v.y, v.z, v.w};
        int mb = lr >> 4, gg = lr & 7, hr = (lr >> 3) & 1;
        int kc = kb4 >> 3, kh = (kb4 >> 2) & 1;
        int j  = hr + 2 * kh;
        int wb = (kc * 4 + mb) * 33 + gg;
#pragma unroll
        for (int i = 0; i < 4; i++) {
            unsigned hb = f2tf32(va[i]);
            unsigned lb = f2tf32(va[i] - __uint_as_float(hb));
            Qp[j * QPL + wb + 8 * i]       = __uint_as_float(hb);
            Qp[(4 + j) * QPL + wb + 8 * i] = __uint_as_float(lb);
        }
    }

    float oacc[2][2][4];
    float lsum[4];
#pragma unroll
    for (int mb = 0; mb < 2; mb++)
#pragma unroll
        for (int nt = 0; nt < 2; nt++)
#pragma unroll
            for (int i = 0; i < 4; i++) oacc[mb][nt][i] = 0.f;
#pragma unroll
    for (int i = 0; i < 4; i++) lsum[i] = 0.f;

    for (int kt = 0; kt < cN; kt += 64) {
        __syncthreads();   // prev-iter Pp/Vp readers done (covers Q on iter 0)

        // ---- K tile (64 keys x 64 d) -> B-planes hi/lo ----
#pragma unroll
        for (int rep = 0; rep < 4; rep++) {
            int db4 = lq4 + rep * 16;
            float4 v = *(const float4*)(kb + (size_t)(kt + lr) * cD + db4);
            float va[4] = {v.x, v.y, v.z, v.w};
            int ntg = lr >> 3, gg = lr & 7;
            int kc = db4 >> 3, pl = (db4 >> 2) & 1;
            int wb = (kc * 8 + ntg) * 33 + gg;
#pragma unroll
            for (int i = 0; i < 4; i++) {
                unsigned hb = f2tf32(va[i]);
                unsigned lb = f2tf32(va[i] - __uint_as_float(hb));
                Kp[pl * KPL + wb + 8 * i]       = __uint_as_float(hb);
                Kp[(2 + pl) * KPL + wb + 8 * i] = __uint_as_float(lb);
            }
        }
        // ---- V tile (64 keys x 64 d) -> B-planes single (n=d, k=key) ----
#pragma unroll
        for (int rep = 0; rep < 4; rep++) {
            int db4 = lq4 + rep * 16;
            float4 v = *(const float4*)(vb + (size_t)(kt + lr) * cD + db4);
            float va[4] = {v.x, v.y, v.z, v.w};
            int kc = lr >> 3, ik = lr & 3, pl = (lr >> 2) & 1;
            int wb = (kc * 8 + (db4 >> 3)) * 33 + (db4 & 7) + 8 * ik;
#pragma unroll
            for (int t = 0; t < 4; t++)
                Vp[pl * VPL + wb + t] = __uint_as_float(f2tf32(va[t]));
        }
        __syncthreads();

        // ---- S = Q K^T (3-term split tf32) ----
        float sacc[2][2][4];
#pragma unroll
        for (int mb = 0; mb < 2; mb++)
#pragma unroll
            for (int nt = 0; nt < 2; nt++)
#pragma unroll
                for (int i = 0; i < 4; i++) sacc[mb][nt][i] = 0.f;

#pragma unroll
        for (int kc = 0; kc < 8; kc++) {
            unsigned bh0[2], bh1[2], bl0[2], bl1[2];
#pragma unroll
            for (int nt = 0; nt < 2; nt++) {
                int off = (kc * 8 + wn * 2 + nt) * 33 + g + 8 * c;
                bh0[nt] = __float_as_uint(Kp[off]);
                bh1[nt] = __float_as_uint(Kp[KPL + off]);
                bl0[nt] = __float_as_uint(Kp[2 * KPL + off]);
                bl1[nt] = __float_as_uint(Kp[3 * KPL + off]);
            }
#pragma unroll
            for (int mb = 0; mb < 2; mb++) {
                int aoff = (kc * 4 + wm * 2 + mb) * 33 + c * 8 + g;
                unsigned ah[4], al[4];
#pragma unroll
                for (int j = 0; j < 4; j++) {
                    ah[j] = __float_as_uint(Qp[j * QPL + aoff]);
                    al[j] = __float_as_uint(Qp[(4 + j) * QPL + aoff]);
                }
#pragma unroll
                for (int nt = 0; nt < 2; nt++) {
                    mma_tf32(sacc[mb][nt], ah, bh0[nt], bh1[nt]);
                    mma_tf32(sacc[mb][nt], ah, bl0[nt], bl1[nt]);
                    mma_tf32(sacc[mb][nt], al, bh0[nt], bh1[nt]);
                }
            }
        }

        // ---- P = exp(S/8): lsum (unrounded) + write tf32 P into A-planes ----
#pragma unroll
        for (int mb = 0; mb < 2; mb++) {
#pragma unroll
            for (int nt = 0; nt < 2; nt++) {
                int blk = ((wn * 2 + nt) * 4 + wm * 2 + mb) * 33 + g;
#pragma unroll
                for (int e = 0; e < 4; e++) {
                    int hr = e >> 1, cc = e & 1;
                    float p = __expf(sacc[mb][nt][e] * 0.125f);
                    lsum[mb * 2 + hr] += p;
                    int nlow = 2 * c + cc;
                    int j  = hr + 2 * (nlow >> 2);
                    Pp[j * PPL + blk + 8 * (nlow & 3)] =
                        __uint_as_float(f2tf32(p));
                }
            }
        }
        __syncthreads();

        // ---- O += P * V (single-term tf32) ----
#pragma unroll
        for (int kc = 0; kc < 8; kc++) {
            unsigned vb0[2], vb1[2];
#pragma unroll
            for (int nt = 0; nt < 2; nt++) {
                int off = (kc * 8 + wn * 2 + nt) * 33 + g + 8 * c;
                vb0[nt] = __float_as_uint(Vp[off]);
                vb1[nt] = __float_as_uint(Vp[VPL + off]);
            }
#pragma unroll
            for (int mb = 0; mb < 2; mb++) {
                int aoff = (kc * 4 + wm * 2 + mb) * 33 + c * 8 + g;
                unsigned ap[4];
#pragma unroll
                for (int j = 0; j < 4; j++)
                    ap[j] = __float_as_uint(Pp[j * PPL + aoff]);
#pragma unroll
                for (int nt = 0; nt < 2; nt++)
                    mma_tf32(oacc[mb][nt], ap, vb0[nt], vb1[nt]);
            }
        }
    }

    // ---- lsum: reduce over c lanes, combine across the 4 n-warps ----
#pragma unroll
    for (int r = 0; r < 4; r++) {
        lsum[r] += __shfl_xor_sync(0xffffffffu, lsum[r], 1);
        lsum[r] += __shfl_xor_sync(0xffffffffu, lsum[r], 2);
    }
    if (c == 0) {
#pragma unroll
        for (int mb = 0; mb < 2; mb++)
#pragma unroll
            for (int hr = 0; hr < 2; hr++) {
                int row = wm * 32 + mb * 16 + g + hr * 8;
                Ls[wn * 64 + row] = lsum[mb * 2 + hr];
            }
    }
    __syncthreads();

    // ---- write out: out[b][q0+row][h*64 + d] ----
    int bb = bh >> 4;
    int h  = bh & 15;
#pragma unroll
    for (int mb = 0; mb < 2; mb++) {
#pragma unroll
        for (int hr = 0; hr < 2; hr++) {
            int row = wm * 32 + mb * 16 + g + hr * 8;
            float lt = Ls[row] + Ls[64 + row] + Ls[128 + row] + Ls[192 + row];
            float inv = 1.0f / lt;
            size_t base = ((size_t)(bb * cN + q0 + row)) * cDIM + h * cD;
#pragma unroll
            for (int nt = 0; nt < 2; nt++) {
                int d = wn * 16 + nt * 8 + 2 * c;
                float2 r2;
                r2.x = oacc[mb][nt][hr * 2 + 0] * inv;
                r2.y = oacc[mb][nt][hr * 2 + 1] * inv;
                *(float2*)(out + base + d) = r2;
            }
        }
    }
}

// ---------------------------------------------------------------------------
extern "C" void kernel_launch(void* const* d_in, const int* in_sizes, int n_in,
                              void* d_out, int out_size) {
    const float* x        = (const float*)d_in[0];
    const float* qkv_w    = (const float*)d_in[1];
    const float* qkv_b    = (const float*)d_in[2];
    const float* q_norm_w = (const float*)d_in[3];
    const float* k_norm_w = (const float*)d_in[4];
    float* out = (float*)d_out;

    const int attn_smem = ATTN_SMEM_WORDS * (int)sizeof(float);  // 102976 B

    // Idempotent, not a stream op (graph-capture safe); no static guard.
    cudaFuncSetAttribute(attn, cudaFuncAttributeMaxDynamicSharedMemorySize,
                         attn_smem);

    dim3 g1(cE / 128, cM / 128);         // 24 x 32
    qkv_gemm<<<g1, 256>>>(x, qkv_w, qkv_b);

    dim3 g2((cB * cH * cN) / 8, 2);      // 8192 x 2
    rmsnorm<<<g2, 256>>>(q_norm_w, k_norm_w);

    dim3 g3(cN / 64, cB * cH);           // 32 x 32
    attn<<<g3, 256, attn_smem>>>(out);
}